// round 2
// baseline (speedup 1.0000x reference)
#include <cuda_runtime.h>
#include <cuda_bf16.h>

// Problem constants
#define B   32
#define C   128
#define H   64
#define W   64
#define KM  4      // number of mixing kernels
#define O   256
#define RED 32
#define HW  4096   // H*W
#define KDIM 1152  // C*9

// Scratch (device globals — no allocation)
__device__ float g_pooled[B * C];          // [B,C]
__device__ float g_att[B * KM];            // [B,K]
__device__ float g_wk[(size_t)B * O * KDIM]; // [B,O,C,3,3]  ~37.7MB

// ---------------------------------------------------------------------------
// 1) Global average pool: pooled[b,c] = mean(x[b,c,:,:])
// ---------------------------------------------------------------------------
__global__ void pool_kernel(const float* __restrict__ x) {
    int bc = blockIdx.x;                       // 0..B*C-1
    const float* p = x + (size_t)bc * HW;
    float s = 0.f;
    for (int i = threadIdx.x; i < HW; i += 256) s += p[i];
    // warp reduce
    #pragma unroll
    for (int o = 16; o; o >>= 1) s += __shfl_down_sync(0xFFFFFFFFu, s, o);
    __shared__ float sm[8];
    if ((threadIdx.x & 31) == 0) sm[threadIdx.x >> 5] = s;
    __syncthreads();
    if (threadIdx.x < 8) {
        float v = sm[threadIdx.x];
        #pragma unroll
        for (int o = 4; o; o >>= 1) v += __shfl_down_sync(0xFFu, v, o);
        if (threadIdx.x == 0) g_pooled[bc] = v * (1.f / (float)HW);
    }
}

// ---------------------------------------------------------------------------
// 2) Attention: h = relu(pooled @ w1^T + b1); att = softmax(h @ w2^T + b2)
//    One thread per batch sample.
// ---------------------------------------------------------------------------
__global__ void attn_kernel(const float* __restrict__ w1, const float* __restrict__ b1,
                            const float* __restrict__ w2, const float* __restrict__ b2) {
    int b = threadIdx.x;
    if (b >= B) return;
    const float* pb = g_pooled + b * C;
    float h[RED];
    #pragma unroll 4
    for (int r = 0; r < RED; r++) {
        float s = b1[r];
        const float* wr = w1 + r * C;
        #pragma unroll 8
        for (int c = 0; c < C; c++) s += pb[c] * wr[c];
        h[r] = fmaxf(s, 0.f);
    }
    float logits[KM];
    float mx = -1e30f;
    #pragma unroll
    for (int k = 0; k < KM; k++) {
        float s = b2[k];
        const float* wr = w2 + k * RED;
        #pragma unroll
        for (int r = 0; r < RED; r++) s += h[r] * wr[r];
        logits[k] = s;
        mx = fmaxf(mx, s);
    }
    float den = 0.f;
    #pragma unroll
    for (int k = 0; k < KM; k++) { logits[k] = __expf(logits[k] - mx); den += logits[k]; }
    float inv = 1.f / den;
    #pragma unroll
    for (int k = 0; k < KM; k++) g_att[b * KM + k] = logits[k] * inv;
}

// ---------------------------------------------------------------------------
// 3) Mix kernels: wk[b,o,:] = sum_k att[b,k] * weights[k,o,:]   (float4)
// ---------------------------------------------------------------------------
__global__ void mix_kernel(const float* __restrict__ weights) {
    const int per_b4 = O * (KDIM / 4);   // 73728 float4 per batch (== per-k stride too)
    int i = blockIdx.x * 256 + threadIdx.x;
    if (i >= B * per_b4) return;
    int b = i / per_b4;
    int rem = i - b * per_b4;
    float a0 = g_att[b * KM + 0], a1 = g_att[b * KM + 1];
    float a2 = g_att[b * KM + 2], a3 = g_att[b * KM + 3];
    const float4* w4 = (const float4*)weights;
    float4 v0 = w4[0 * per_b4 + rem];
    float4 v1 = w4[1 * per_b4 + rem];
    float4 v2 = w4[2 * per_b4 + rem];
    float4 v3 = w4[3 * per_b4 + rem];
    float4 r;
    r.x = a0 * v0.x + a1 * v1.x + a2 * v2.x + a3 * v3.x;
    r.y = a0 * v0.y + a1 * v1.y + a2 * v2.y + a3 * v3.y;
    r.z = a0 * v0.z + a1 * v1.z + a2 * v2.z + a3 * v3.z;
    r.w = a0 * v0.w + a1 * v1.w + a2 * v2.w + a3 * v3.w;
    ((float4*)g_wk)[i] = r;
}

// ---------------------------------------------------------------------------
// 4) Per-sample conv as implicit GEMM:
//    out[b][m][n] = sum_k wk[b][m][k] * im2col_x[b][k][n]
//    M=256 (o), N=4096 (pixels), K=1152 (c*9).  128x128x8 tiles, 8x8 per thread.
// ---------------------------------------------------------------------------
#define BM 128
#define BN 128
#define BK 8

__global__ void __launch_bounds__(256, 2)
conv_kernel(const float* __restrict__ x, float* __restrict__ out) {
    int b  = blockIdx.z;
    int m0 = blockIdx.y * BM;
    int n0 = blockIdx.x * BN;

    const float* A = g_wk + (size_t)b * O * KDIM;    // [256][1152]
    const float* X = x    + (size_t)b * C * HW;      // [128][64][64]
    float*       Ob = out + (size_t)b * O * HW;      // [256][4096]

    __shared__ float As[BK][BM];
    __shared__ float Bs[BK][BN];

    int tid = threadIdx.x;
    int tm = tid >> 4;        // 0..15
    int tn = tid & 15;        // 0..15

    // A tile load mapping: 128 rows x 8 cols; each thread loads one float4
    int arow = tid >> 1;            // 0..127
    int acol = (tid & 1) * 4;       // 0 or 4
    // B tile load mapping: 8 k-rows x 128 n-cols; each thread builds one float4
    int bkr = tid >> 5;             // 0..7
    int bnc = (tid & 31) * 4;       // 0..124

    float acc[8][8];
    #pragma unroll
    for (int i = 0; i < 8; i++)
        #pragma unroll
        for (int j = 0; j < 8; j++) acc[i][j] = 0.f;

    for (int k0 = 0; k0 < KDIM; k0 += BK) {
        // --- load A tile (wk), transpose into As[k][m] ---
        float4 av = *(const float4*)(A + (size_t)(m0 + arow) * KDIM + k0 + acol);
        As[acol + 0][arow] = av.x;
        As[acol + 1][arow] = av.y;
        As[acol + 2][arow] = av.z;
        As[acol + 3][arow] = av.w;

        // --- load B tile via on-the-fly im2col ---
        int kg = k0 + bkr;
        int c  = kg / 9;
        int r  = kg - c * 9;
        int dy = r / 3 - 1;
        int dx = r - (r / 3) * 3 - 1;
        const float* Xc = X + c * HW;
        float4 bv;
        {
            int n = n0 + bnc;
            int y = n >> 6, xx = n & 63;
            int iy = y + dy;
            float v0 = 0.f, v1 = 0.f, v2 = 0.f, v3 = 0.f;
            if ((unsigned)iy < (unsigned)H) {
                const float* row = Xc + iy * W;
                int ix0 = xx + dx;
                if ((unsigned)(ix0 + 0) < (unsigned)W) v0 = row[ix0 + 0];
                if ((unsigned)(ix0 + 1) < (unsigned)W) v1 = row[ix0 + 1];
                if ((unsigned)(ix0 + 2) < (unsigned)W) v2 = row[ix0 + 2];
                if ((unsigned)(ix0 + 3) < (unsigned)W) v3 = row[ix0 + 3];
            }
            bv = make_float4(v0, v1, v2, v3);
        }
        *(float4*)&Bs[bkr][bnc] = bv;

        __syncthreads();

        #pragma unroll
        for (int kk = 0; kk < BK; kk++) {
            float4 a0 = *(const float4*)&As[kk][tm * 8];
            float4 a1 = *(const float4*)&As[kk][tm * 8 + 4];
            float4 b0 = *(const float4*)&Bs[kk][tn * 8];
            float4 b1 = *(const float4*)&Bs[kk][tn * 8 + 4];
            float aa[8] = {a0.x, a0.y, a0.z, a0.w, a1.x, a1.y, a1.z, a1.w};
            float bb[8] = {b0.x, b0.y, b0.z, b0.w, b1.x, b1.y, b1.z, b1.w};
            #pragma unroll
            for (int i = 0; i < 8; i++)
                #pragma unroll
                for (int j = 0; j < 8; j++)
                    acc[i][j] += aa[i] * bb[j];
        }
        __syncthreads();
    }

    // --- write 8x8 micro-tile ---
    #pragma unroll
    for (int i = 0; i < 8; i++) {
        float* op = Ob + (size_t)(m0 + tm * 8 + i) * HW + n0 + tn * 8;
        ((float4*)op)[0] = make_float4(acc[i][0], acc[i][1], acc[i][2], acc[i][3]);
        ((float4*)op)[1] = make_float4(acc[i][4], acc[i][5], acc[i][6], acc[i][7]);
    }
}

// ---------------------------------------------------------------------------
extern "C" void kernel_launch(void* const* d_in, const int* in_sizes, int n_in,
                              void* d_out, int out_size) {
    const float* x       = (const float*)d_in[0];
    const float* weights = (const float*)d_in[1];
    const float* w1      = (const float*)d_in[2];
    const float* b1      = (const float*)d_in[3];
    const float* w2      = (const float*)d_in[4];
    const float* b2      = (const float*)d_in[5];
    float* out = (float*)d_out;

    pool_kernel<<<B * C, 256>>>(x);
    attn_kernel<<<1, 32>>>(w1, b1, w2, b2);
    {
        int total4 = B * O * (KDIM / 4);
        mix_kernel<<<(total4 + 255) / 256, 256>>>(weights);
    }
    {
        dim3 grid(HW / BN, O / BM, B);   // (32, 2, 32)
        conv_kernel<<<grid, 256>>>(x, out);
    }
}

// round 4
// speedup vs baseline: 2.5137x; 2.5137x over previous
#include <cuda_runtime.h>
#include <cuda_bf16.h>
#include <cstdint>

#define B   32
#define C   128
#define H   64
#define W   64
#define KM  4
#define O   256
#define RED 32
#define HW  4096
#define KDIM 1152

// ---------------- device scratch (module globals, no allocation) ------------
__device__ float g_pooled[B * C];
__device__ float g_att[B * KM];
__device__ __align__(256) __nv_bfloat16 g_xhi[(size_t)B * HW * C];
__device__ __align__(256) __nv_bfloat16 g_xlo[(size_t)B * HW * C];
__device__ __align__(256) __nv_bfloat16 g_whi[(size_t)B * O * 9 * C];
__device__ __align__(256) __nv_bfloat16 g_wlo[(size_t)B * O * 9 * C];

// ---------------- PTX helpers (all family-independent: sm_80+) -------------
__device__ __forceinline__ uint32_t smem_to_u32(const void* p) {
    uint32_t a;
    asm("{ .reg .u64 t; cvta.to.shared.u64 t, %1; cvt.u32.u64 %0, t; }" : "=r"(a) : "l"(p));
    return a;
}
__device__ __forceinline__ void cpa16(uint32_t dst, const void* src) {
    asm volatile("cp.async.cg.shared.global [%0], [%1], 16;" :: "r"(dst), "l"(src) : "memory");
}
__device__ __forceinline__ void cpa16z(uint32_t dst, const void* src, int sz) {
    asm volatile("cp.async.cg.shared.global [%0], [%1], 16, %2;" :: "r"(dst), "l"(src), "r"(sz) : "memory");
}
#define CP_COMMIT()  asm volatile("cp.async.commit_group;" ::: "memory")
#define CP_WAIT0()   asm volatile("cp.async.wait_group 0;" ::: "memory")

#define LDSM_X4(r, addr) \
    asm volatile("ldmatrix.sync.aligned.m8n8.x4.shared.b16 {%0,%1,%2,%3}, [%4];" \
        : "=r"((r)[0]), "=r"((r)[1]), "=r"((r)[2]), "=r"((r)[3]) : "r"(addr))

__device__ __forceinline__ void mma16816(float* d, const uint32_t* a, uint32_t b0, uint32_t b1) {
    asm volatile("mma.sync.aligned.m16n8k16.row.col.f32.bf16.bf16.f32 "
        "{%0,%1,%2,%3}, {%4,%5,%6,%7}, {%8,%9}, {%0,%1,%2,%3};"
        : "+f"(d[0]), "+f"(d[1]), "+f"(d[2]), "+f"(d[3])
        : "r"(a[0]), "r"(a[1]), "r"(a[2]), "r"(a[3]), "r"(b0), "r"(b1));
}

// ---------------------------------------------------------------------------
// 1) Global average pool
// ---------------------------------------------------------------------------
__global__ void pool_kernel(const float* __restrict__ x) {
    int bc = blockIdx.x;
    const float* p = x + (size_t)bc * HW;
    float s = 0.f;
    for (int i = threadIdx.x; i < HW; i += 256) s += p[i];
    #pragma unroll
    for (int o = 16; o; o >>= 1) s += __shfl_down_sync(0xFFFFFFFFu, s, o);
    __shared__ float sm[8];
    if ((threadIdx.x & 31) == 0) sm[threadIdx.x >> 5] = s;
    __syncthreads();
    if (threadIdx.x < 8) {
        float v = sm[threadIdx.x];
        #pragma unroll
        for (int o = 4; o; o >>= 1) v += __shfl_down_sync(0xFFu, v, o);
        if (threadIdx.x == 0) g_pooled[bc] = v * (1.f / (float)HW);
    }
}

// ---------------------------------------------------------------------------
// 2) Attention MLP + softmax (one thread per batch)
// ---------------------------------------------------------------------------
__global__ void attn_kernel(const float* __restrict__ w1, const float* __restrict__ b1,
                            const float* __restrict__ w2, const float* __restrict__ b2) {
    int b = threadIdx.x;
    if (b >= B) return;
    const float* pb = g_pooled + b * C;
    float h[RED];
    #pragma unroll 4
    for (int r = 0; r < RED; r++) {
        float s = b1[r];
        const float* wr = w1 + r * C;
        #pragma unroll 8
        for (int c = 0; c < C; c++) s += pb[c] * wr[c];
        h[r] = fmaxf(s, 0.f);
    }
    float logits[KM];
    float mx = -1e30f;
    #pragma unroll
    for (int k = 0; k < KM; k++) {
        float s = b2[k];
        const float* wr = w2 + k * RED;
        #pragma unroll
        for (int r = 0; r < RED; r++) s += h[r] * wr[r];
        logits[k] = s; mx = fmaxf(mx, s);
    }
    float den = 0.f;
    #pragma unroll
    for (int k = 0; k < KM; k++) { logits[k] = __expf(logits[k] - mx); den += logits[k]; }
    float inv = 1.f / den;
    #pragma unroll
    for (int k = 0; k < KM; k++) g_att[b * KM + k] = logits[k] * inv;
}

// ---------------------------------------------------------------------------
// 3) wk mix -> [b][o][tap][c] bf16 hi/lo.  One block per (o, b), 128 threads.
// ---------------------------------------------------------------------------
__global__ void wk_kernel(const float* __restrict__ weights) {
    int o = blockIdx.x, b = blockIdx.y;
    float a0 = g_att[b * KM + 0], a1 = g_att[b * KM + 1];
    float a2 = g_att[b * KM + 2], a3 = g_att[b * KM + 3];
    __shared__ __nv_bfloat16 shi[9 * C], slo[9 * C];
    const size_t ks = (size_t)O * KDIM;
    const float* wp = weights + (size_t)o * KDIM;
    for (int i = threadIdx.x; i < KDIM; i += 128) {
        float v = a0 * wp[i] + a1 * wp[ks + i] + a2 * wp[2 * ks + i] + a3 * wp[3 * ks + i];
        __nv_bfloat16 hi = __float2bfloat16(v);
        int c = i / 9, tap = i - c * 9;          // weights inner layout [c][tap]
        shi[tap * C + c] = hi;
        slo[tap * C + c] = __float2bfloat16(v - __bfloat162float(hi));
    }
    __syncthreads();
    size_t ob = ((size_t)b * O + o) * KDIM;
    uint4* dh = (uint4*)(g_whi + ob);
    uint4* dl = (uint4*)(g_wlo + ob);
    const uint4* sh = (const uint4*)shi;
    const uint4* sl = (const uint4*)slo;
    for (int i = threadIdx.x; i < (KDIM * 2) / 16; i += 128) { dh[i] = sh[i]; dl[i] = sl[i]; }
}

// ---------------------------------------------------------------------------
// 4) x transpose -> xT[b][pix][c] bf16 hi/lo.  Block = 64 pixels x 128 c.
// ---------------------------------------------------------------------------
__global__ void xt_kernel(const float* __restrict__ x) {
    int b = blockIdx.y;
    int p0 = blockIdx.x * 64;
    __shared__ float sm[64][C + 1];
    const float* xb = x + (size_t)b * C * HW + p0;
    for (int idx = threadIdx.x; idx < 64 * C; idx += 256) {
        int c = idx >> 6, p = idx & 63;
        sm[p][c] = xb[(size_t)c * HW + p];
    }
    __syncthreads();
    __nv_bfloat16* oh = g_xhi + ((size_t)b * HW + p0) * C;
    __nv_bfloat16* ol = g_xlo + ((size_t)b * HW + p0) * C;
    for (int idx = threadIdx.x; idx < 64 * C; idx += 256) {
        int p = idx >> 7, c = idx & 127;
        float v = sm[p][c];
        __nv_bfloat16 hi = __float2bfloat16(v);
        oh[(size_t)p * C + c] = hi;
        ol[(size_t)p * C + c] = __float2bfloat16(v - __bfloat162float(hi));
    }
}

// ---------------------------------------------------------------------------
// 5) Conv GEMM via mma.sync (bf16 3-pass split).
//    CTA: M=128 x N=256.  8 warps, warp tile 32x128.
//    18 stages of K=64 (9 taps x 2 c-halves), cp.async double buffer.
// ---------------------------------------------------------------------------
#define RPADB   144                       // padded row stride in bytes (72 bf16)
#define A_ROWS  128
#define B_ROWS  256
#define AT_BYTES (A_ROWS * RPADB)         // 18432
#define BT_BYTES (B_ROWS * RPADB)         // 36864
#define OFF_AH  0
#define OFF_AL  (AT_BYTES)
#define OFF_BH  (2 * AT_BYTES)
#define OFF_BL  (2 * AT_BYTES + BT_BYTES)
#define STAGE_BYTES (2 * AT_BYTES + 2 * BT_BYTES)   // 110592
#define NSTAGE  18
#define CONV_SMEM (2 * STAGE_BYTES)                 // 221184

__global__ void __launch_bounds__(256, 1) conv_kernel(float* __restrict__ out) {
    extern __shared__ char smem[];
    uint32_t sb = smem_to_u32(smem);
    int tid = threadIdx.x;
    int lane = tid & 31, wid = tid >> 5;
    int b  = blockIdx.z;
    int m0 = blockIdx.y * 128;
    int n0 = blockIdx.x * 256;
    int wm = (wid & 3) * 32;       // warp M offset within CTA
    int wn = (wid >> 2) * 128;     // warp N offset within CTA

    const __nv_bfloat16* whi = g_whi + ((size_t)b * O + m0) * KDIM;
    const __nv_bfloat16* wlo = g_wlo + ((size_t)b * O + m0) * KDIM;
    const __nv_bfloat16* xhi = g_xhi + (size_t)b * HW * C;
    const __nv_bfloat16* xlo = g_xlo + (size_t)b * HW * C;

    int row8  = tid >> 3;          // 0..31
    int chunk = tid & 7;           // 16B chunk within 128B of k-data

    auto load_stage = [&](int s) {
        uint32_t base = sb + (uint32_t)(s & 1) * STAGE_BYTES;
        int tap = s >> 1, chalf = s & 1;
        int dy = tap / 3 - 1, dx = tap % 3 - 1;
        size_t koff = (size_t)tap * 128 + chalf * 64 + chunk * 8;
        #pragma unroll
        for (int j = 0; j < 4; j++) {
            int row = row8 + j * 32;
            uint32_t doff = (uint32_t)row * RPADB + (uint32_t)chunk * 16;
            cpa16(base + OFF_AH + doff, whi + (size_t)row * KDIM + koff);
            cpa16(base + OFF_AL + doff, wlo + (size_t)row * KDIM + koff);
        }
        #pragma unroll
        for (int j = 0; j < 8; j++) {
            int row = row8 + j * 32;
            int p = n0 + row;
            int iy = (p >> 6) + dy, ix = (p & 63) + dx;
            bool valid = ((unsigned)iy < 64u) && ((unsigned)ix < 64u);
            int q = valid ? (p + dy * 64 + dx) : 0;
            int sz = valid ? 16 : 0;
            size_t so = (size_t)q * C + chalf * 64 + chunk * 8;
            uint32_t doff = (uint32_t)row * RPADB + (uint32_t)chunk * 16;
            cpa16z(base + OFF_BH + doff, xhi + so, sz);
            cpa16z(base + OFF_BL + doff, xlo + so, sz);
        }
        CP_COMMIT();
    };

    float acc[2][16][4];
    #pragma unroll
    for (int i = 0; i < 2; i++)
        #pragma unroll
        for (int j = 0; j < 16; j++)
            #pragma unroll
            for (int q = 0; q < 4; q++) acc[i][j][q] = 0.f;

    load_stage(0);

    // ldmatrix lane geometry (non-trans for both operands; k-contiguous rows)
    uint32_t a_row = (uint32_t)(wm + (lane & 15));
    uint32_t a_kb  = (uint32_t)((lane >> 4) * 16);            // +8 elems = +16B
    uint32_t b_row = (uint32_t)(wn + (lane & 7) + ((lane >> 4) & 1) * 8);
    uint32_t b_kb  = (uint32_t)(((lane >> 3) & 1) * 16);

    #pragma unroll 1
    for (int s = 0; s < NSTAGE; s++) {
        CP_WAIT0();
        __syncthreads();
        if (s + 1 < NSTAGE) load_stage(s + 1);

        uint32_t base = sb + (uint32_t)(s & 1) * STAGE_BYTES;
        #pragma unroll
        for (int kk = 0; kk < 4; kk++) {
            uint32_t kb = (uint32_t)(kk * 32);      // k16 step in bytes
            uint32_t ah[2][4], al[2][4];
            #pragma unroll
            for (int mt = 0; mt < 2; mt++) {
                uint32_t off = (a_row + mt * 16) * RPADB + kb + a_kb;
                LDSM_X4(ah[mt], base + OFF_AH + off);
                LDSM_X4(al[mt], base + OFF_AL + off);
            }
            #pragma unroll
            for (int g = 0; g < 8; g++) {
                uint32_t off = (b_row + g * 16) * RPADB + kb + b_kb;
                uint32_t bh[4], bl[4];
                LDSM_X4(bh, base + OFF_BH + off);
                LDSM_X4(bl, base + OFF_BL + off);
                #pragma unroll
                for (int mt = 0; mt < 2; mt++) {
                    #pragma unroll
                    for (int nt = 0; nt < 2; nt++) {
                        float* d = acc[mt][g * 2 + nt];
                        mma16816(d, ah[mt], bh[nt * 2], bh[nt * 2 + 1]);   // hi*hi
                        mma16816(d, al[mt], bh[nt * 2], bh[nt * 2 + 1]);   // lo*hi
                        mma16816(d, ah[mt], bl[nt * 2], bl[nt * 2 + 1]);   // hi*lo
                    }
                }
            }
        }
    }

    // epilogue: d0,d1 -> (row, 2c), d2,d3 -> (row+8, 2c)
    float* ob = out + ((size_t)b * O + m0) * HW + n0;
    #pragma unroll
    for (int mt = 0; mt < 2; mt++) {
        int r = wm + mt * 16 + (lane >> 2);
        #pragma unroll
        for (int nti = 0; nti < 16; nti++) {
            int cn = wn + nti * 8 + 2 * (lane & 3);
            float2 v0 = make_float2(acc[mt][nti][0], acc[mt][nti][1]);
            float2 v1 = make_float2(acc[mt][nti][2], acc[mt][nti][3]);
            *(float2*)(ob + (size_t)r * HW + cn) = v0;
            *(float2*)(ob + (size_t)(r + 8) * HW + cn) = v1;
        }
    }
}

// ---------------------------------------------------------------------------
extern "C" void kernel_launch(void* const* d_in, const int* in_sizes, int n_in,
                              void* d_out, int out_size) {
    const float* x       = (const float*)d_in[0];
    const float* weights = (const float*)d_in[1];
    const float* w1      = (const float*)d_in[2];
    const float* b1      = (const float*)d_in[3];
    const float* w2      = (const float*)d_in[4];
    const float* b2      = (const float*)d_in[5];
    float* out = (float*)d_out;

    pool_kernel<<<B * C, 256>>>(x);
    attn_kernel<<<1, 32>>>(w1, b1, w2, b2);
    wk_kernel<<<dim3(O, B), 128>>>(weights);
    xt_kernel<<<dim3(HW / 64, B), 256>>>(x);

    cudaFuncSetAttribute(conv_kernel, cudaFuncAttributeMaxDynamicSharedMemorySize, CONV_SMEM);
    conv_kernel<<<dim3(HW / 256, O / 128, B), 256, CONV_SMEM>>>(out);
}

// round 5
// speedup vs baseline: 4.3132x; 1.7159x over previous
#include <cuda_runtime.h>
#include <cuda_fp16.h>
#include <cstdint>

#define B   32
#define C   128
#define H   64
#define W   64
#define KM  4
#define O   256
#define RED 32
#define HW  4096
#define KDIM 1152

// ---------------- device scratch (module globals, no allocation) ------------
__device__ float g_pooled[B * C];
__device__ float g_att[B * KM];
__device__ __align__(256) __half g_xt[(size_t)B * HW * C];      // xT [b][pix][c]
__device__ __align__(256) __half g_wk[(size_t)B * O * 9 * C];   // wk [b][o][tap][c]

// ---------------- PTX helpers (family-independent: sm_80+) -------------
__device__ __forceinline__ uint32_t smem_to_u32(const void* p) {
    uint32_t a;
    asm("{ .reg .u64 t; cvta.to.shared.u64 t, %1; cvt.u32.u64 %0, t; }" : "=r"(a) : "l"(p));
    return a;
}
__device__ __forceinline__ void cpa16(uint32_t dst, const void* src) {
    asm volatile("cp.async.cg.shared.global [%0], [%1], 16;" :: "r"(dst), "l"(src) : "memory");
}
__device__ __forceinline__ void cpa16z(uint32_t dst, const void* src, int sz) {
    asm volatile("cp.async.cg.shared.global [%0], [%1], 16, %2;" :: "r"(dst), "l"(src), "r"(sz) : "memory");
}
#define CP_COMMIT()  asm volatile("cp.async.commit_group;" ::: "memory")
#define CP_WAIT0()   asm volatile("cp.async.wait_group 0;" ::: "memory")

#define LDSM_X4(r, addr) \
    asm volatile("ldmatrix.sync.aligned.m8n8.x4.shared.b16 {%0,%1,%2,%3}, [%4];" \
        : "=r"((r)[0]), "=r"((r)[1]), "=r"((r)[2]), "=r"((r)[3]) : "r"(addr))

__device__ __forceinline__ void mma16816(float* d, const uint32_t* a, uint32_t b0, uint32_t b1) {
    asm volatile("mma.sync.aligned.m16n8k16.row.col.f32.f16.f16.f32 "
        "{%0,%1,%2,%3}, {%4,%5,%6,%7}, {%8,%9}, {%0,%1,%2,%3};"
        : "+f"(d[0]), "+f"(d[1]), "+f"(d[2]), "+f"(d[3])
        : "r"(a[0]), "r"(a[1]), "r"(a[2]), "r"(a[3]), "r"(b0), "r"(b1));
}

// ---------------------------------------------------------------------------
// 1) Global average pool
// ---------------------------------------------------------------------------
__global__ void pool_kernel(const float* __restrict__ x) {
    int bc = blockIdx.x;
    const float* p = x + (size_t)bc * HW;
    float s = 0.f;
    for (int i = threadIdx.x; i < HW; i += 256) s += p[i];
    #pragma unroll
    for (int o = 16; o; o >>= 1) s += __shfl_down_sync(0xFFFFFFFFu, s, o);
    __shared__ float sm[8];
    if ((threadIdx.x & 31) == 0) sm[threadIdx.x >> 5] = s;
    __syncthreads();
    if (threadIdx.x < 8) {
        float v = sm[threadIdx.x];
        #pragma unroll
        for (int o = 4; o; o >>= 1) v += __shfl_down_sync(0xFFu, v, o);
        if (threadIdx.x == 0) g_pooled[bc] = v * (1.f / (float)HW);
    }
}

// ---------------------------------------------------------------------------
// 2) Attention MLP + softmax (one thread per batch)
// ---------------------------------------------------------------------------
__global__ void attn_kernel(const float* __restrict__ w1, const float* __restrict__ b1,
                            const float* __restrict__ w2, const float* __restrict__ b2) {
    int b = threadIdx.x;
    if (b >= B) return;
    const float* pb = g_pooled + b * C;
    float h[RED];
    #pragma unroll 4
    for (int r = 0; r < RED; r++) {
        float s = b1[r];
        const float* wr = w1 + r * C;
        #pragma unroll 8
        for (int c = 0; c < C; c++) s += pb[c] * wr[c];
        h[r] = fmaxf(s, 0.f);
    }
    float logits[KM];
    float mx = -1e30f;
    #pragma unroll
    for (int k = 0; k < KM; k++) {
        float s = b2[k];
        const float* wr = w2 + k * RED;
        #pragma unroll
        for (int r = 0; r < RED; r++) s += h[r] * wr[r];
        logits[k] = s; mx = fmaxf(mx, s);
    }
    float den = 0.f;
    #pragma unroll
    for (int k = 0; k < KM; k++) { logits[k] = __expf(logits[k] - mx); den += logits[k]; }
    float inv = 1.f / den;
    #pragma unroll
    for (int k = 0; k < KM; k++) g_att[b * KM + k] = logits[k] * inv;
}

// ---------------------------------------------------------------------------
// 3) wk mix -> [b][o][tap][c] fp16.  One block per (o, b), 128 threads.
// ---------------------------------------------------------------------------
__global__ void wk_kernel(const float* __restrict__ weights) {
    int o = blockIdx.x, b = blockIdx.y;
    float a0 = g_att[b * KM + 0], a1 = g_att[b * KM + 1];
    float a2 = g_att[b * KM + 2], a3 = g_att[b * KM + 3];
    __shared__ __half sh[9 * C];
    const size_t ks = (size_t)O * KDIM;
    const float* wp = weights + (size_t)o * KDIM;
    for (int i = threadIdx.x; i < KDIM; i += 128) {
        float v = a0 * wp[i] + a1 * wp[ks + i] + a2 * wp[2 * ks + i] + a3 * wp[3 * ks + i];
        int c = i / 9, tap = i - c * 9;          // weights inner layout [c][tap]
        sh[tap * C + c] = __float2half_rn(v);
    }
    __syncthreads();
    size_t ob = ((size_t)b * O + o) * KDIM;
    uint4* dh = (uint4*)(g_wk + ob);
    const uint4* shv = (const uint4*)sh;
    for (int i = threadIdx.x; i < (KDIM * 2) / 16; i += 128) dh[i] = shv[i];
}

// ---------------------------------------------------------------------------
// 4) x transpose -> xT[b][pix][c] fp16.  Block = 64 pixels x 128 c.
// ---------------------------------------------------------------------------
__global__ void xt_kernel(const float* __restrict__ x) {
    int b = blockIdx.y;
    int p0 = blockIdx.x * 64;
    __shared__ float sm[64][C + 1];
    const float* xb = x + (size_t)b * C * HW + p0;
    for (int idx = threadIdx.x; idx < 64 * C; idx += 256) {
        int c = idx >> 6, p = idx & 63;
        sm[p][c] = xb[(size_t)c * HW + p];
    }
    __syncthreads();
    __half* oh = g_xt + ((size_t)b * HW + p0) * C;
    for (int idx = threadIdx.x; idx < 64 * C; idx += 256) {
        int p = idx >> 7, c = idx & 127;
        oh[(size_t)p * C + c] = __float2half_rn(sm[p][c]);
    }
}

// ---------------------------------------------------------------------------
// 5) Conv GEMM via mma.sync fp16 single-pass.
//    CTA: M=128 x N=256.  8 warps, warp tile 32x128.
//    18 stages of K=64 (9 taps x 2 c-halves), cp.async double buffer.
// ---------------------------------------------------------------------------
#define RPADB   144                       // padded row stride in bytes (72 halves)
#define A_ROWS  128
#define B_ROWS  256
#define AT_BYTES (A_ROWS * RPADB)         // 18432
#define BT_BYTES (B_ROWS * RPADB)         // 36864
#define OFF_A   0
#define OFF_B   (AT_BYTES)
#define STAGE_BYTES (AT_BYTES + BT_BYTES) // 55296
#define NSTAGE  18
#define CONV_SMEM (2 * STAGE_BYTES)       // 110592

__global__ void __launch_bounds__(256, 1) conv_kernel(float* __restrict__ out) {
    extern __shared__ char smem[];
    uint32_t sb = smem_to_u32(smem);
    int tid = threadIdx.x;
    int lane = tid & 31, wid = tid >> 5;
    int b  = blockIdx.z;
    int m0 = blockIdx.y * 128;
    int n0 = blockIdx.x * 256;
    int wm = (wid & 3) * 32;       // warp M offset within CTA
    int wn = (wid >> 2) * 128;     // warp N offset within CTA

    const __half* wk = g_wk + ((size_t)b * O + m0) * KDIM;
    const __half* xt = g_xt + (size_t)b * HW * C;

    int row8  = tid >> 3;          // 0..31
    int chunk = tid & 7;           // 16B chunk within 128B of k-data

    auto load_stage = [&](int s) {
        uint32_t base = sb + (uint32_t)(s & 1) * STAGE_BYTES;
        int tap = s >> 1, chalf = s & 1;
        int dy = tap / 3 - 1, dx = tap % 3 - 1;
        size_t koff = (size_t)tap * 128 + chalf * 64 + chunk * 8;
        #pragma unroll
        for (int j = 0; j < 4; j++) {
            int row = row8 + j * 32;
            uint32_t doff = (uint32_t)row * RPADB + (uint32_t)chunk * 16;
            cpa16(base + OFF_A + doff, wk + (size_t)row * KDIM + koff);
        }
        #pragma unroll
        for (int j = 0; j < 8; j++) {
            int row = row8 + j * 32;
            int p = n0 + row;
            int iy = (p >> 6) + dy, ix = (p & 63) + dx;
            bool valid = ((unsigned)iy < 64u) && ((unsigned)ix < 64u);
            int q = valid ? (p + dy * 64 + dx) : 0;
            int sz = valid ? 16 : 0;
            size_t so = (size_t)q * C + chalf * 64 + chunk * 8;
            uint32_t doff = (uint32_t)row * RPADB + (uint32_t)chunk * 16;
            cpa16z(base + OFF_B + doff, xt + so, sz);
        }
        CP_COMMIT();
    };

    float acc[2][16][4];
    #pragma unroll
    for (int i = 0; i < 2; i++)
        #pragma unroll
        for (int j = 0; j < 16; j++)
            #pragma unroll
            for (int q = 0; q < 4; q++) acc[i][j][q] = 0.f;

    load_stage(0);

    // ldmatrix lane geometry (non-trans for both operands; k-contiguous rows)
    uint32_t a_row = (uint32_t)(wm + (lane & 15));
    uint32_t a_kb  = (uint32_t)((lane >> 4) * 16);            // +8 elems = +16B
    uint32_t b_row = (uint32_t)(wn + (lane & 7) + ((lane >> 4) & 1) * 8);
    uint32_t b_kb  = (uint32_t)(((lane >> 3) & 1) * 16);

    #pragma unroll 1
    for (int s = 0; s < NSTAGE; s++) {
        CP_WAIT0();
        __syncthreads();
        if (s + 1 < NSTAGE) load_stage(s + 1);

        uint32_t base = sb + (uint32_t)(s & 1) * STAGE_BYTES;
        #pragma unroll
        for (int kk = 0; kk < 4; kk++) {
            uint32_t kb = (uint32_t)(kk * 32);      // k16 step in bytes
            uint32_t ah[2][4];
            #pragma unroll
            for (int mt = 0; mt < 2; mt++) {
                uint32_t off = (a_row + mt * 16) * RPADB + kb + a_kb;
                LDSM_X4(ah[mt], base + OFF_A + off);
            }
            #pragma unroll
            for (int g = 0; g < 8; g++) {
                uint32_t off = (b_row + g * 16) * RPADB + kb + b_kb;
                uint32_t bh[4];
                LDSM_X4(bh, base + OFF_B + off);
                #pragma unroll
                for (int mt = 0; mt < 2; mt++) {
                    #pragma unroll
                    for (int nt = 0; nt < 2; nt++) {
                        mma16816(acc[mt][g * 2 + nt], ah[mt], bh[nt * 2], bh[nt * 2 + 1]);
                    }
                }
            }
        }
    }

    // epilogue: d0,d1 -> (row, 2c), d2,d3 -> (row+8, 2c)
    float* ob = out + ((size_t)b * O + m0) * HW + n0;
    #pragma unroll
    for (int mt = 0; mt < 2; mt++) {
        int r = wm + mt * 16 + (lane >> 2);
        #pragma unroll
        for (int nti = 0; nti < 16; nti++) {
            int cn = wn + nti * 8 + 2 * (lane & 3);
            float2 v0 = make_float2(acc[mt][nti][0], acc[mt][nti][1]);
            float2 v1 = make_float2(acc[mt][nti][2], acc[mt][nti][3]);
            *(float2*)(ob + (size_t)r * HW + cn) = v0;
            *(float2*)(ob + (size_t)(r + 8) * HW + cn) = v1;
        }
    }
}

// ---------------------------------------------------------------------------
extern "C" void kernel_launch(void* const* d_in, const int* in_sizes, int n_in,
                              void* d_out, int out_size) {
    const float* x       = (const float*)d_in[0];
    const float* weights = (const float*)d_in[1];
    const float* w1      = (const float*)d_in[2];
    const float* b1      = (const float*)d_in[3];
    const float* w2      = (const float*)d_in[4];
    const float* b2      = (const float*)d_in[5];
    float* out = (float*)d_out;

    pool_kernel<<<B * C, 256>>>(x);
    attn_kernel<<<1, 32>>>(w1, b1, w2, b2);
    wk_kernel<<<dim3(O, B), 128>>>(weights);
    xt_kernel<<<dim3(HW / 64, B), 256>>>(x);

    cudaFuncSetAttribute(conv_kernel, cudaFuncAttributeMaxDynamicSharedMemorySize, CONV_SMEM);
    conv_kernel<<<dim3(HW / 256, O / 128, B), 256, CONV_SMEM>>>(out);
}